// round 13
// baseline (speedup 1.0000x reference)
#include <cuda_runtime.h>
#include <cuda_fp16.h>
#include <math.h>

typedef unsigned long long ull;
typedef unsigned int uint;

#define NB 2
#define MTOT 4768
#define SC_CLAMP 4.135166556742356f
#define NEG_S -10000.0f
#define BBAND 5000
#define GPX 16
#define PXCAP 8192
#define BKCAP 24576

// ----------------- static scratch -----------------
__device__ float  g_wt[2304 * 256];                  // [k = ic*9+tap][oc] fp32
__device__ __half g_wth[2304 * 256];                 // same, fp16
__device__ float  g_deltas[(size_t)NB * 196608 * 4];
__device__ ull    g_keys[(size_t)NB * 196608];       // approx keys (full L)
__device__ ull    g_bkeys[NB * BKCAP];               // exact keys (compact band)
__device__ ull    g_thresh[NB];
__device__ int    g_cnt[NB];
__device__ ull    g_sel[NB * 1024];
__device__ int    g_pxflag[NB * 65536];
__device__ int    g_pxcnt[NB];
__device__ int    g_px[NB * PXCAP];
__device__ float  g_cscore[NB * MTOT];
__device__ float4 g_cbox[NB * MTOT];
__device__ float4 g_cobox[NB * MTOT];
__device__ int    g_cvalid[NB * MTOT];
__device__ ull    g_gkey[NB * MTOT];
__device__ int    g_order[NB * MTOT];
__device__ ull    g_mask[(size_t)NB * 5 * 1000 * 16];
__device__ int    g_keep[NB * MTOT];

__device__ __forceinline__ uint f2ord(float s) {
    uint u = __float_as_uint(s);
    return (u & 0x80000000u) ? ~u : (u | 0x80000000u);
}
__device__ __forceinline__ float ord2f(uint o) {
    uint u = (o & 0x80000000u) ? (o & 0x7FFFFFFFu) : ~o;
    return __uint_as_float(u);
}

// ----------------- weight transpose: w[oc][ic][tap] -> g_wt/g_wth[ic*9+tap][oc] ------------
__global__ void k_transpose_w(const float* __restrict__ w) {
    int idx = blockIdx.x * 256 + threadIdx.x;
    if (idx >= 2304 * 256) return;
    int oc = idx & 255;
    int k = idx >> 8;
    int ic = k / 9, tap = k - ic * 9;
    float v = w[(oc * 256 + ic) * 9 + tap];
    g_wt[idx] = v;
    g_wth[idx] = __float2half(v);
}

// ----------------- APPROX: fp16 m16n8k16 tensor-core conv + fused objectness head ----------
// Block tile: 64 px (M) x 256 oc (N), k = 2304 in 16-chunks. 8 warps: 2(px) x 4(oc),
// warp tile 32px x 64oc = 2 m-tiles x 8 n-tiles of m16n8k16.
#define MMA_F16(c, a0, a1, a2, a3, b0, b1)                               \
    asm("mma.sync.aligned.m16n8k16.row.col.f32.f16.f16.f32 "             \
        "{%0,%1,%2,%3}, {%4,%5,%6,%7}, {%8,%9}, {%0,%1,%2,%3};"          \
        : "+f"(c[0]), "+f"(c[1]), "+f"(c[2]), "+f"(c[3])                 \
        : "r"(a0), "r"(a1), "r"(a2), "r"(a3), "r"(b0), "r"(b1))

__global__ void k_tconv(const float* __restrict__ x, const float* __restrict__ bconv,
                        const float* __restrict__ wobj, const float* __restrict__ bobj,
                        int S, int logS, int L) {
    const int P = S * S;
    const int b = blockIdx.y;
    const int p0 = blockIdx.x * 64;
    const float* xin = x + (size_t)b * 256 * P;

    __shared__ __align__(16) char sbuf[33792];       // phase1: sAh+sBh; phase2: sT
    __shared__ float sWo[768];
    __shared__ float sBias[256];
    __shared__ float sBo[3];
    __half (*sAh)[26] = (__half(*)[26])sbuf;             // [px 64][k 16] pitch 26
    __half (*sBh)[26] = (__half(*)[26])(sbuf + 3328);    // [oc 256][k 16] pitch 26
    __half (*sT)[264] = (__half(*)[264])sbuf;            // [px 64][oc 256] pitch 264

    const int tid = threadIdx.x;
    const int lane = tid & 31;
    const int wid = tid >> 5;
    const int wr = wid & 1;          // px half (32)
    const int wc = wid >> 1;         // oc quarter (64)
    const int qid = lane >> 2;       // 0..7 (group id)
    const int qt = lane & 3;         // 0..3 (thread in group)
    const int pxb = wr * 32;
    const int ocb0 = wc * 64;

    for (int i = tid; i < 768; i += 256) sWo[i] = wobj[i];
    if (tid < 256) sBias[tid] = bconv[tid];
    if (tid < 3) sBo[tid] = bobj[tid];

    const int tpx = tid & 63;
    const int rg = (tid >> 6) * 4;
    const int gp = p0 + tpx;
    const int y = gp >> logS;
    const int xq = gp & (S - 1);

    float c[2][8][4];
#pragma unroll
    for (int m = 0; m < 2; m++)
#pragma unroll
        for (int n = 0; n < 8; n++)
#pragma unroll
            for (int r = 0; r < 4; r++) c[m][n][r] = 0.f;

    for (int tap = 0; tap < 9; tap++) {
        const int t3 = tap / 3;
        const int dy = t3 - 1, dx = tap - t3 * 3 - 1;
        const int yy = y + dy, xx = xq + dx;
        const bool ok = ((uint)yy < (uint)S) && ((uint)xx < (uint)S);
        const int off = yy * S + xx;
        for (int icb = 0; icb < 256; icb += 16) {
            // weights chunk: oc = tid row, 16 k halves (coalesced global half reads)
#pragma unroll 4
            for (int i = 0; i < 16; i++)
                sBh[tid][i] = g_wth[(size_t)((icb + i) * 9 + tap) * 256 + tid];
            // input chunk: px = tpx row, 4 k halves per thread
#pragma unroll
            for (int i = 0; i < 4; i++)
                sAh[tpx][rg + i] = __float2half(ok ? xin[(size_t)(icb + rg + i) * P + off] : 0.f);
            __syncthreads();
            // B fragments: b0 = k{2qt,2qt+1} @ oc gid, b1 = k{2qt+8,2qt+9}
            uint bf[8][2];
#pragma unroll
            for (int n = 0; n < 8; n++) {
                const __half* bp = sBh[ocb0 + n * 8 + qid];
                bf[n][0] = *(const uint*)&bp[2 * qt];
                bf[n][1] = *(const uint*)&bp[2 * qt + 8];
            }
#pragma unroll
            for (int m = 0; m < 2; m++) {
                const int pxr = pxb + m * 16;
                uint a0 = *(const uint*)&sAh[pxr + qid][2 * qt];
                uint a1 = *(const uint*)&sAh[pxr + qid + 8][2 * qt];
                uint a2 = *(const uint*)&sAh[pxr + qid][2 * qt + 8];
                uint a3 = *(const uint*)&sAh[pxr + qid + 8][2 * qt + 8];
#pragma unroll
                for (int n = 0; n < 8; n++)
                    MMA_F16(c[m][n], a0, a1, a2, a3, bf[n][0], bf[n][1]);
            }
            __syncthreads();
        }
    }

    // epilogue: bias + relu -> half sT[px][oc]
#pragma unroll
    for (int m = 0; m < 2; m++)
#pragma unroll
        for (int n = 0; n < 8; n++) {
            int pxl = pxb + m * 16 + qid;
            int oc = ocb0 + n * 8 + 2 * qt;
            float t0 = fmaxf(c[m][n][0] + sBias[oc], 0.f);
            float t1 = fmaxf(c[m][n][1] + sBias[oc + 1], 0.f);
            *(__half2*)&sT[pxl][oc] = __floats2half2_rn(t0, t1);
            float t2 = fmaxf(c[m][n][2] + sBias[oc], 0.f);
            float t3v = fmaxf(c[m][n][3] + sBias[oc + 1], 0.f);
            *(__half2*)&sT[pxl + 8][oc] = __floats2half2_rn(t2, t3v);
        }
    __syncthreads();

    // fused approx objectness head: 64 px x 3 anchors
    if (tid < 192) {
        int pxl = tid / 3, a = tid - pxl * 3;
        const float* wr_ = &sWo[a * 256];
        float s = 0.f;
        for (int oc = 0; oc < 256; oc++)
            s = fmaf(wr_[oc], __half2float(sT[pxl][oc]), s);
        s += sBo[a];
        int i = (p0 + pxl) * 3 + a;
        g_keys[(size_t)b * L + i] = ((ull)f2ord(s) << 32) | (uint)(~(uint)i);
    }
}

// ----------------- radix-select k-th largest (npass bytes; src 0=approx full, 1=band) ------
__global__ void k_select(int src, int Lfix, int k, int npass) {
    __shared__ int hist[256];
    __shared__ ull sprefix;
    __shared__ int sr;
    int b = blockIdx.x;
    int tid = threadIdx.x;
    const ull* keys;
    int L;
    if (src == 0) { keys = g_keys + (size_t)b * Lfix; L = Lfix; }
    else          { keys = g_bkeys + b * BKCAP;       L = 3 * g_pxcnt[b]; }
    ull prefix = 0;
    int r = k;
    for (int pass = 0; pass < npass; pass++) {
        if (tid < 256) hist[tid] = 0;
        __syncthreads();
        int bsh = 56 - 8 * pass;
        for (int i = tid; i < L; i += 1024) {
            ull key = keys[i];
            bool m = (pass == 0) || ((key >> (64 - 8 * pass)) == prefix);
            if (m) atomicAdd(&hist[(int)((key >> bsh) & 255)], 1);
        }
        __syncthreads();
        if (tid == 0) {
            int acc = 0, byte = 0;
            for (int v = 255; v >= 0; v--) {
                if (acc + hist[v] >= r) { byte = v; break; }
                acc += hist[v];
            }
            sprefix = (prefix << 8) | (uint)byte;
            sr = r - acc;
        }
        __syncthreads();
        prefix = sprefix;
        r = sr;
        __syncthreads();
    }
    if (tid == 0) { g_thresh[b] = prefix << (64 - 8 * npass); g_cnt[b] = 0; }
}

// ----------------- band: zero flags/counts, mark banded pixels, compact list ---------------
__global__ void k_zeroflag(int P) {
    int id = blockIdx.x * 256 + threadIdx.x;
    if (id < NB * P) g_pxflag[id] = 0;
    if (id < NB) g_pxcnt[id] = 0;
}
__global__ void k_bandmark(int L, int P) {
    int id = blockIdx.x * 256 + threadIdx.x;
    if (id >= NB * L) return;
    int n = id / L, i = id - n * L;
    if (g_keys[(size_t)n * L + i] >= g_thresh[n]) g_pxflag[n * P + i / 3] = 1;
}
__global__ void k_pxcompact(int P) {
    int id = blockIdx.x * 256 + threadIdx.x;
    if (id >= NB * P) return;
    int n = id / P, px = id - n * P;
    if (g_pxflag[id]) {
        int pos = atomicAdd(&g_pxcnt[n], 1);
        if (pos < PXCAP) g_px[n * PXCAP + pos] = px;
    }
}

// ----------------- EXACT: gather conv (canonical fmaf chain) + fused 15-ch head ------------
__global__ __launch_bounds__(256)
void k_econv(const float* __restrict__ x, const float* __restrict__ bconv,
             const float* __restrict__ wobj, const float* __restrict__ bobj,
             const float* __restrict__ wdel, const float* __restrict__ bdel,
             int S, int logS, int L) {
    const int P = S * S;
    const int b = blockIdx.y;
    int cnt = g_pxcnt[b];
    int base = blockIdx.x * GPX;
    if (base >= cnt) return;
    int tid = threadIdx.x;

    __shared__ float w15s[15 * 256];
    __shared__ float b15[15];
    __shared__ __align__(16) float pool[32 * 9 * GPX];   // reused as srt[16][257]
    __shared__ int spx[GPX], spy[GPX], spxc[GPX];

    for (int i = tid; i < 3 * 256; i += 256) w15s[i] = wobj[i];
    for (int i = tid; i < 12 * 256; i += 256) w15s[768 + i] = wdel[i];
    if (tid < 3) b15[tid] = bobj[tid];
    else if (tid < 15) b15[tid] = bdel[tid - 3];

    int npx = cnt - base; if (npx > GPX) npx = GPX;
    if (tid < GPX) {
        int p = (tid < npx) ? g_px[b * PXCAP + base + tid] : 0;
        spx[tid] = p; spy[tid] = p >> logS; spxc[tid] = p & (S - 1);
    }
    __syncthreads();

    float acc[GPX];
#pragma unroll
    for (int j = 0; j < GPX; j++) acc[j] = 0.f;
    const float* xin = x + (size_t)b * 256 * P;

    for (int icb = 0; icb < 256; icb += 32) {
        for (int idx = tid; idx < 32 * 9 * GPX; idx += 256) {
            int px = idx & (GPX - 1);
            int r = idx >> 4;
            int icL = r / 9, tap = r - icL * 9;
            int t3 = tap / 3;
            int dy = t3 - 1, dx = tap - t3 * 3 - 1;
            int yy = spy[px] + dy, xx = spxc[px] + dx;
            float v = 0.f;
            if ((uint)yy < (uint)S && (uint)xx < (uint)S)
                v = xin[(size_t)(icb + icL) * P + yy * S + xx];
            pool[idx] = v;
        }
        __syncthreads();
        for (int icL = 0; icL < 32; icL++) {
#pragma unroll
            for (int tap = 0; tap < 9; tap++) {
                float w = g_wt[(size_t)((icb + icL) * 9 + tap) * 256 + tid];
                const float* sp = &pool[(icL * 9 + tap) * GPX];
                float4 v0 = *(const float4*)(sp);
                float4 v1 = *(const float4*)(sp + 4);
                float4 v2 = *(const float4*)(sp + 8);
                float4 v3 = *(const float4*)(sp + 12);
                acc[0]  = fmaf(w, v0.x, acc[0]);  acc[1]  = fmaf(w, v0.y, acc[1]);
                acc[2]  = fmaf(w, v0.z, acc[2]);  acc[3]  = fmaf(w, v0.w, acc[3]);
                acc[4]  = fmaf(w, v1.x, acc[4]);  acc[5]  = fmaf(w, v1.y, acc[5]);
                acc[6]  = fmaf(w, v1.z, acc[6]);  acc[7]  = fmaf(w, v1.w, acc[7]);
                acc[8]  = fmaf(w, v2.x, acc[8]);  acc[9]  = fmaf(w, v2.y, acc[9]);
                acc[10] = fmaf(w, v2.z, acc[10]); acc[11] = fmaf(w, v2.w, acc[11]);
                acc[12] = fmaf(w, v3.x, acc[12]); acc[13] = fmaf(w, v3.y, acc[13]);
                acc[14] = fmaf(w, v3.z, acc[14]); acc[15] = fmaf(w, v3.w, acc[15]);
            }
        }
        __syncthreads();
    }

    float bsc = bconv[tid];
#pragma unroll
    for (int px = 0; px < GPX; px++)
        pool[px * 257 + tid] = fmaxf(__fadd_rn(acc[px], bsc), 0.f);
    __syncthreads();

    if (tid < 15 * GPX) {
        int px = tid / 15, cch = tid - px * 15;
        if (px < npx) {
            float s = 0.f;
            const float* wr = &w15s[cch * 256];
            const float* tr = &pool[px * 257];
            for (int oc = 0; oc < 256; oc++) s = fmaf(wr[oc], tr[oc], s);
            s = __fadd_rn(s, b15[cch]);
            int cell = spx[px];
            if (cch < 3) {
                int i = cell * 3 + cch;
                g_bkeys[b * BKCAP + (base + px) * 3 + cch] =
                    ((ull)f2ord(s) << 32) | (uint)(~(uint)i);
            } else {
                int a = (cch - 3) >> 2, comp = (cch - 3) & 3;
                g_deltas[((size_t)b * L + cell * 3 + a) * 4 + comp] = s;
            }
        }
    }
}

// ----------------- compact exact top-k from band keys -----------------
__global__ void k_compactb() {
    int b = blockIdx.y;
    int Lb = 3 * g_pxcnt[b];
    int i = blockIdx.x * 256 + threadIdx.x;
    if (i >= Lb) return;
    ull key = g_bkeys[b * BKCAP + i];
    if (key >= g_thresh[b]) {
        int pos = atomicAdd(&g_cnt[b], 1);
        g_sel[b * 1024 + pos] = key;
    }
}

// ----------------- bitonic sort (desc) + decode (unfused _rn arithmetic) -------------------
__global__ void k_sortdecode(int W, int logW, int stride, float size,
                             int lvl, int k, int off, int L) {
    __shared__ ull skey[1024];
    int b = blockIdx.x;
    int tid = threadIdx.x;
    skey[tid] = (tid < k) ? g_sel[b * 1024 + tid] : 0ull;
    __syncthreads();
    for (int len = 2; len <= 1024; len <<= 1)
        for (int j = len >> 1; j > 0; j >>= 1) {
            int ixj = tid ^ j;
            if (ixj > tid) {
                bool desc = ((tid & len) == 0);
                ull a = skey[tid], c = skey[ixj];
                bool sw = desc ? (a < c) : (a > c);
                if (sw) { skey[tid] = c; skey[ixj] = a; }
            }
            __syncthreads();
        }
    if (tid < k) {
        ull key = skey[tid];
        uint idx = ~(uint)key;
        float s = ord2f((uint)(key >> 32));
        int a = idx % 3;
        int cell = idx / 3;
        int hy = cell >> logW, wx = cell & (W - 1);
        float ratio = (a == 0) ? 0.5f : (a == 1) ? 1.0f : 2.0f;
        float ws = __fdiv_rn(size, __fsqrt_rn(ratio));
        float hs = __fmul_rn(ws, ratio);
        float hws = __fmul_rn(0.5f, ws), hhs = __fmul_rn(0.5f, hs);
        float shx = (float)(wx * stride), shy = (float)(hy * stride);
        float ax1 = __fadd_rn(shx, -hws), ay1 = __fadd_rn(shy, -hhs);
        float ax2 = __fadd_rn(shx, hws),  ay2 = __fadd_rn(shy, hhs);
        const float* d = g_deltas + ((size_t)b * L + idx) * 4;
        float dxv = d[0], dyv = d[1];
        float dw = fminf(d[2], SC_CLAMP), dh = fminf(d[3], SC_CLAMP);
        float aw = __fsub_rn(ax2, ax1), ah = __fsub_rn(ay2, ay1);
        float cx = __fadd_rn(ax1, __fmul_rn(0.5f, aw));
        float cy = __fadd_rn(ay1, __fmul_rn(0.5f, ah));
        float pcx = __fadd_rn(__fmul_rn(dxv, aw), cx);
        float pcy = __fadd_rn(__fmul_rn(dyv, ah), cy);
        float ew = (float)exp((double)dw);
        float eh = (float)exp((double)dh);
        float pw = __fmul_rn(ew, aw), ph = __fmul_rn(eh, ah);
        float hpw = __fmul_rn(0.5f, pw), hph = __fmul_rn(0.5f, ph);
        float x1 = __fsub_rn(pcx, hpw), y1 = __fsub_rn(pcy, hph);
        float x2 = __fadd_rn(pcx, hpw), y2 = __fadd_rn(pcy, hph);
        x1 = fminf(fmaxf(x1, 0.f), 1024.f);
        y1 = fminf(fmaxf(y1, 0.f), 1024.f);
        x2 = fminf(fmaxf(x2, 0.f), 1024.f);
        y2 = fminf(fmaxf(y2, 0.f), 1024.f);
        int valid = (__fsub_rn(x2, x1) > 0.f) && (__fsub_rn(y2, y1) > 0.f);
        int ci = off + tid;
        float lo = (float)lvl * 4096.0f;
        g_cscore[b * MTOT + ci] = s;
        g_cbox[b * MTOT + ci] = make_float4(x1, y1, x2, y2);
        g_cobox[b * MTOT + ci] = make_float4(__fadd_rn(x1, lo), __fadd_rn(y1, lo),
                                             __fadd_rn(x2, lo), __fadd_rn(y2, lo));
        g_cvalid[b * MTOT + ci] = valid;
        g_gkey[b * MTOT + ci] = ((ull)(uint)(key >> 32) << 32) | (uint)(~(uint)ci);
    }
}

// ----------------- global rank via merge of 5 sorted lists -----------------
__global__ void k_rank() {
    int b = blockIdx.y;
    int ci = blockIdx.x * 256 + threadIdx.x;
    if (ci >= MTOT) return;
    const int off[6] = {0, 1000, 2000, 3000, 4000, MTOT};
    ull key = g_gkey[b * MTOT + ci];
    int l = ci / 1000; if (l > 4) l = 4;
    int rank = ci - off[l];
    for (int o = 0; o < 5; o++) {
        if (o == l) continue;
        int lo = off[o], hi = off[o + 1];
        while (lo < hi) {
            int mid = (lo + hi) >> 1;
            if (g_gkey[b * MTOT + mid] > key) lo = mid + 1; else hi = mid;
        }
        rank += lo - off[o];
    }
    g_order[b * MTOT + rank] = ci;
}

// ----------------- NMS suppression bitmasks (unfused _rn IoU) -----------------
__global__ void k_mask() {
    int b = blockIdx.z;
    int l = blockIdx.y;
    int k = (l == 4) ? 768 : 1000;
    int i = blockIdx.x * 8 + threadIdx.y;
    int w = threadIdx.x;
    if (i >= k) return;
    int off = l * 1000;
    float4 A = g_cobox[b * MTOT + off + i];
    float areaA = __fmul_rn(__fsub_rn(A.z, A.x), __fsub_rn(A.w, A.y));
    ull word = 0;
    int jmax = i - w * 64; if (jmax > 64) jmax = 64;
    for (int t = 0; t < jmax; t++) {
        int j = w * 64 + t;
        float4 B = g_cobox[b * MTOT + off + j];
        float areaB = __fmul_rn(__fsub_rn(B.z, B.x), __fsub_rn(B.w, B.y));
        float ltx = fmaxf(A.x, B.x), lty = fmaxf(A.y, B.y);
        float rbx = fminf(A.z, B.z), rby = fminf(A.w, B.w);
        float iw = fmaxf(__fsub_rn(rbx, ltx), 0.f);
        float ih = fmaxf(__fsub_rn(rby, lty), 0.f);
        float inter = __fmul_rn(iw, ih);
        float denom = __fadd_rn(__fsub_rn(__fadd_rn(areaA, areaB), inter), 1e-9f);
        float iou = __fdiv_rn(inter, denom);
        if (iou > 0.7f) word |= 1ull << t;
    }
    g_mask[((size_t)(b * 5 + l) * 1000 + i) * 16 + w] = word;
}

// ----------------- serial greedy NMS scan (1 warp per batch-level) -----------------
__global__ void k_nms() {
    int b = blockIdx.y, l = blockIdx.x;
    int k = (l == 4) ? 768 : 1000;
    int off = l * 1000;
    int lane = threadIdx.x;
    const ull* mbase = g_mask + (size_t)(b * 5 + l) * 1000 * 16;
    ull keepw = 0;
    ull row = (lane < 16) ? mbase[lane] : 0;
    for (int i = 0; i < k; i++) {
        ull nrow = (lane < 16 && i + 1 < k) ? mbase[(size_t)(i + 1) * 16 + lane] : 0;
        bool sup = __any_sync(0xFFFFFFFFu, (row & keepw) != 0);
        int vi = g_cvalid[b * MTOT + off + i];
        int ki = (vi && !sup) ? 1 : 0;
        if (ki && lane == (i >> 6)) keepw |= 1ull << (i & 63);
        if (lane == 0) g_keep[b * MTOT + off + i] = ki;
        row = nrow;
    }
}

// ----------------- stable partition + output -----------------
__global__ void k_out(float* __restrict__ out) {
    __shared__ int flag[MTOT];
    __shared__ int part[1024];
    __shared__ int sK;
    int b = blockIdx.x;
    int tid = threadIdx.x;
    for (int r = tid; r < MTOT; r += 1024)
        flag[r] = g_keep[b * MTOT + g_order[b * MTOT + r]];
    __syncthreads();
    int base = tid * 5;
    int mysum = 0;
#pragma unroll
    for (int j = 0; j < 5; j++) {
        int r = base + j;
        if (r < MTOT) mysum += flag[r];
    }
    part[tid] = mysum;
    __syncthreads();
    for (int d = 1; d < 1024; d <<= 1) {
        int v = (tid >= d) ? part[tid - d] : 0;
        __syncthreads();
        part[tid] += v;
        __syncthreads();
    }
    if (tid == 1023) sK = part[1023];
    __syncthreads();
    int run = part[tid] - mysum;
    int Ktot = sK;
    for (int j = 0; j < 5; j++) {
        int r = base + j;
        if (r >= MTOT) break;
        int ci = g_order[b * MTOT + r];
        int f = flag[r];
        int pos;
        float sc;
        if (f) { pos = run; sc = g_cscore[b * MTOT + ci]; }
        else   { pos = Ktot + (r - run); sc = NEG_S; }
        run += f;
        if (pos < 1000) {
            float4 bx = g_cbox[b * MTOT + ci];
            float* o = out + ((size_t)b * 1000 + pos) * 5;
            o[0] = bx.x; o[1] = bx.y; o[2] = bx.z; o[3] = bx.w; o[4] = sc;
        }
    }
}

// ----------------- launch -----------------
extern "C" void kernel_launch(void* const* d_in, const int* in_sizes, int n_in,
                              void* d_out, int out_size) {
    const float* feats[5] = {(const float*)d_in[0], (const float*)d_in[1],
                             (const float*)d_in[2], (const float*)d_in[3],
                             (const float*)d_in[4]};
    const float* w_conv  = (const float*)d_in[5];
    const float* b_conv  = (const float*)d_in[6];
    const float* w_obj   = (const float*)d_in[7];
    const float* b_obj   = (const float*)d_in[8];
    const float* w_delta = (const float*)d_in[9];
    const float* b_delta = (const float*)d_in[10];
    float* out = (float*)d_out;

    const int   Ss[5]  = {256, 128, 64, 32, 16};
    const int   LG[5]  = {8, 7, 6, 5, 4};
    const int   STm[5] = {4, 8, 16, 32, 64};
    const float SZ[5]  = {32.f, 64.f, 128.f, 256.f, 512.f};
    const int   KL[5]  = {1000, 1000, 1000, 1000, 768};
    const int   OFF[5] = {0, 1000, 2000, 3000, 4000};

    k_transpose_w<<<2304, 256>>>(w_conv);

    for (int l = 0; l < 5; l++) {
        int S = Ss[l], P = S * S, L = P * 3;
        int Bb = (BBAND < L) ? BBAND : L;
        // phase A: fp16 tensor-core conv + fused objectness -> approx keys
        k_tconv<<<dim3(P / 64, NB), 256>>>(feats[l], b_conv, w_obj, b_obj, S, LG[l], L);
        k_select<<<NB, 1024>>>(0, L, Bb, 4);               // approx band threshold (score bits)
        k_zeroflag<<<(NB * P + 255) / 256, 256>>>(P);
        k_bandmark<<<(NB * L + 255) / 256, 256>>>(L, P);
        k_pxcompact<<<(NB * P + 255) / 256, 256>>>(P);
        // phase B: exact recompute on band pixels only -> compact keys
        k_econv<<<dim3(PXCAP / GPX, NB), 256>>>(feats[l], b_conv, w_obj, b_obj,
                                                w_delta, b_delta, S, LG[l], L);
        k_select<<<NB, 1024>>>(1, 0, KL[l], 8);            // exact top-k over band keys
        k_compactb<<<dim3(BKCAP / 256, NB), 256>>>();
        k_sortdecode<<<NB, 1024>>>(S, LG[l], STm[l], SZ[l], l, KL[l], OFF[l], L);
    }

    k_rank<<<dim3((MTOT + 255) / 256, NB), 256>>>();
    k_mask<<<dim3(125, 5, NB), dim3(16, 8)>>>();
    k_nms<<<dim3(5, NB), 32>>>();
    k_out<<<NB, 1024>>>(out);
}

// round 15
// speedup vs baseline: 1.3956x; 1.3956x over previous
#include <cuda_runtime.h>
#include <cuda_fp16.h>
#include <math.h>

typedef unsigned long long ull;
typedef unsigned int uint;

#define NB 2
#define MTOT 4768
#define SC_CLAMP 4.135166556742356f
#define NEG_S -10000.0f
#define BBAND 5000
#define GPX 16
#define PXCAP 8192
#define BKCAP 24576
#define TDYN 83456

// ----------------- static scratch -----------------
__device__ float  g_wt[2304 * 256];                  // [k = ic*9+tap][oc] fp32
__device__ __half g_wth[2304 * 256];                 // same, fp16
__device__ float  g_deltas[(size_t)NB * 196608 * 4];
__device__ ull    g_keys[(size_t)NB * 196608];       // approx keys (full L)
__device__ ull    g_bkeys[NB * BKCAP];               // exact keys (compact band)
__device__ ull    g_thresh[NB];
__device__ int    g_cnt[NB];
__device__ ull    g_sel[NB * 1024];
__device__ int    g_pxflag[NB * 65536];
__device__ int    g_pxcnt[NB];
__device__ int    g_px[NB * PXCAP];
__device__ float  g_cscore[NB * MTOT];
__device__ float4 g_cbox[NB * MTOT];
__device__ float4 g_cobox[NB * MTOT];
__device__ int    g_cvalid[NB * MTOT];
__device__ ull    g_gkey[NB * MTOT];
__device__ int    g_order[NB * MTOT];
__device__ ull    g_mask[(size_t)NB * 5 * 1000 * 16];
__device__ int    g_keep[NB * MTOT];

__device__ __forceinline__ uint f2ord(float s) {
    uint u = __float_as_uint(s);
    return (u & 0x80000000u) ? ~u : (u | 0x80000000u);
}
__device__ __forceinline__ float ord2f(uint o) {
    uint u = (o & 0x80000000u) ? (o & 0x7FFFFFFFu) : ~o;
    return __uint_as_float(u);
}

// ----------------- weight transpose: w[oc][ic][tap] -> g_wt/g_wth[ic*9+tap][oc] ------------
__global__ void k_transpose_w(const float* __restrict__ w) {
    int idx = blockIdx.x * 256 + threadIdx.x;
    if (idx >= 2304 * 256) return;
    int oc = idx & 255;
    int k = idx >> 8;
    int ic = k / 9, tap = k - ic * 9;
    float v = w[(oc * 256 + ic) * 9 + tap];
    g_wt[idx] = v;
    g_wth[idx] = __float2half(v);
}

// ----------------- APPROX: halo-tiled fp16 MMA conv + fused objectness head ----------------
// Block: 128 px 2D tile (R x C) x 256 oc. 16 ic-chunks; each chunk stages halo input once
// and all 9 taps' weights, then runs 9 taps x 32 MMAs/warp. 8 warps: 4(px32) x 2(oc128).
#define MMA_F16(c, a0, a1, a2, a3, b0, b1)                               \
    asm("mma.sync.aligned.m16n8k16.row.col.f32.f16.f16.f32 "             \
        "{%0,%1,%2,%3}, {%4,%5,%6,%7}, {%8,%9}, {%0,%1,%2,%3};"          \
        : "+f"(c[0]), "+f"(c[1]), "+f"(c[2]), "+f"(c[3])                 \
        : "r"(a0), "r"(a1), "r"(a2), "r"(a3), "r"(b0), "r"(b1))

__global__ __launch_bounds__(256, 1)
void k_tconv(const float* __restrict__ x, const float* __restrict__ bconv,
             const float* __restrict__ wobj, const float* __restrict__ bobj,
             int S, int logC, int L) {
    const int P = S * S;
    const int C = 1 << logC;         // tile cols (32, or 16 for S=16)
    const int R = 128 >> logC;       // tile rows
    const int Wh = C + 2;            // halo width
    const int Nh = (R + 2) * Wh;     // halo pixels
    const int b = blockIdx.y;
    const int bi = blockIdx.x;
    const int ntx = S >> logC;
    const int by0 = (bi / ntx) * R;
    const int bx0 = (bi - (bi / ntx) * ntx) * C;
    const float* xin = x + (size_t)b * 256 * P;

    extern __shared__ char dsm[];
    __half* dynW = (__half*)dsm;                     // [tap*16+k][264]  (76032 B)
    __half* dynA = (__half*)(dsm + 76032);           // [halo px][18]    (7344 B)
    __half (*sT)[264] = (__half(*)[264])dsm;         // epilogue reuse: [128 px][256 oc]

    __shared__ float sWo[768];
    __shared__ float sBias[256];
    __shared__ float sBo[3];

    const int tid = threadIdx.x;
    const int lane = tid & 31;
    const int wid = tid >> 5;
    const int qid = lane >> 2;
    const int qt = lane & 3;
    const int pxb = (wid & 3) * 32;
    const int ocb = (wid >> 2) * 128;

    for (int i = tid; i < 768; i += 256) sWo[i] = wobj[i];
    if (tid < 256) sBias[tid] = bconv[tid];
    if (tid < 3) sBo[tid] = bobj[tid];

    // per-thread halo row bases: halo coord of (lprow+dy, col+dx) = (lprow+t3)*Wh + col+(dx+1),
    // with t3 = dy+1 folded into the tap offset -> base carries NO +1 shifts.
    int rb[2][2];
#pragma unroll
    for (int m = 0; m < 2; m++) {
        int lp0 = pxb + m * 16 + qid;
        int lp1 = lp0 + 8;
        rb[m][0] = (lp0 >> logC) * Wh + (lp0 & (C - 1));
        rb[m][1] = (lp1 >> logC) * Wh + (lp1 & (C - 1));
    }

    float c[2][16][4];
#pragma unroll
    for (int m = 0; m < 2; m++)
#pragma unroll
        for (int n = 0; n < 16; n++)
#pragma unroll
            for (int r = 0; r < 4; r++) c[m][n][r] = 0.f;

    for (int icb = 0; icb < 256; icb += 16) {
        // stage weights: 144 rows (tap*16+k) x 32 oc-groups of 8 halves (conflict-free uint4)
        for (int idx = tid; idx < 4608; idx += 256) {
            int r = idx >> 5, g8 = idx & 31;
            int tap = r >> 4, i = r & 15;
            uint4 v = *(const uint4*)(g_wth + (size_t)((icb + i) * 9 + tap) * 256 + g8 * 8);
            *(uint4*)(dynW + r * 264 + g8 * 8) = v;
        }
        // stage input halo: [halo px][16 ic], zero-padded at image borders
        for (int idx = tid; idx < 16 * Nh; idx += 256) {
            int i = idx / Nh, h = idx - i * Nh;
            int hy = h / Wh, hx = h - hy * Wh;
            int gy = by0 + hy - 1, gx = bx0 + hx - 1;
            float v = ((uint)gy < (uint)S && (uint)gx < (uint)S)
                          ? xin[(size_t)(icb + i) * P + gy * S + gx] : 0.f;
            dynA[h * 18 + i] = __float2half(v);
        }
        __syncthreads();
#pragma unroll
        for (int tap = 0; tap < 9; tap++) {
            const int t3 = tap / 3;
            const int to = t3 * Wh + (tap - 3 * t3);   // (dy+1)*Wh + (dx+1)
            uint a[2][4];
#pragma unroll
            for (int m = 0; m < 2; m++) {
                const __half* p0 = dynA + (rb[m][0] + to) * 18;
                const __half* p1 = dynA + (rb[m][1] + to) * 18;
                a[m][0] = *(const uint*)(p0 + 2 * qt);
                a[m][1] = *(const uint*)(p1 + 2 * qt);
                a[m][2] = *(const uint*)(p0 + 2 * qt + 8);
                a[m][3] = *(const uint*)(p1 + 2 * qt + 8);
            }
            const __half* w0 = dynW + (tap * 16 + 2 * qt) * 264;
            const __half* w1 = w0 + 264;
            const __half* w8 = w0 + 8 * 264;
            const __half* w9 = w8 + 264;
#pragma unroll
            for (int n = 0; n < 16; n++) {
                int oc = ocb + n * 8 + qid;
                __half2 b0h = __halves2half2(w0[oc], w1[oc]);
                __half2 b1h = __halves2half2(w8[oc], w9[oc]);
                uint b0 = *reinterpret_cast<uint*>(&b0h);
                uint b1 = *reinterpret_cast<uint*>(&b1h);
                MMA_F16(c[0][n], a[0][0], a[0][1], a[0][2], a[0][3], b0, b1);
                MMA_F16(c[1][n], a[1][0], a[1][1], a[1][2], a[1][3], b0, b1);
            }
        }
        __syncthreads();
    }

    // epilogue: bias + relu -> half sT[px][oc] (reuses dyn smem)
#pragma unroll
    for (int m = 0; m < 2; m++)
#pragma unroll
        for (int n = 0; n < 16; n++) {
            int pxl = pxb + m * 16 + qid;
            int oc = ocb + n * 8 + 2 * qt;
            float t0 = fmaxf(c[m][n][0] + sBias[oc], 0.f);
            float t1 = fmaxf(c[m][n][1] + sBias[oc + 1], 0.f);
            *(__half2*)&sT[pxl][oc] = __floats2half2_rn(t0, t1);
            float t2 = fmaxf(c[m][n][2] + sBias[oc], 0.f);
            float t3v = fmaxf(c[m][n][3] + sBias[oc + 1], 0.f);
            *(__half2*)&sT[pxl + 8][oc] = __floats2half2_rn(t2, t3v);
        }
    __syncthreads();

    // fused approx objectness head: 128 px x 3 anchors
    for (int idx = tid; idx < 384; idx += 256) {
        int lp = idx / 3, a = idx - lp * 3;
        const float* wr_ = &sWo[a * 256];
        float s = 0.f;
        for (int oc = 0; oc < 256; oc++)
            s = fmaf(wr_[oc], __half2float(sT[lp][oc]), s);
        s += sBo[a];
        int g = (by0 + (lp >> logC)) * S + bx0 + (lp & (C - 1));
        int i = g * 3 + a;
        g_keys[(size_t)b * L + i] = ((ull)f2ord(s) << 32) | (uint)(~(uint)i);
    }
}

// ----------------- radix-select k-th largest (npass bytes; src 0=approx full, 1=band) ------
__global__ void k_select(int src, int Lfix, int k, int npass) {
    __shared__ int hist[256];
    __shared__ ull sprefix;
    __shared__ int sr;
    int b = blockIdx.x;
    int tid = threadIdx.x;
    const ull* keys;
    int L;
    if (src == 0) { keys = g_keys + (size_t)b * Lfix; L = Lfix; }
    else          { keys = g_bkeys + b * BKCAP;       L = 3 * g_pxcnt[b]; }
    ull prefix = 0;
    int r = k;
    for (int pass = 0; pass < npass; pass++) {
        if (tid < 256) hist[tid] = 0;
        __syncthreads();
        int bsh = 56 - 8 * pass;
        for (int i = tid; i < L; i += 1024) {
            ull key = keys[i];
            bool m = (pass == 0) || ((key >> (64 - 8 * pass)) == prefix);
            if (m) atomicAdd(&hist[(int)((key >> bsh) & 255)], 1);
        }
        __syncthreads();
        if (tid == 0) {
            int acc = 0, byte = 0;
            for (int v = 255; v >= 0; v--) {
                if (acc + hist[v] >= r) { byte = v; break; }
                acc += hist[v];
            }
            sprefix = (prefix << 8) | (uint)byte;
            sr = r - acc;
        }
        __syncthreads();
        prefix = sprefix;
        r = sr;
        __syncthreads();
    }
    if (tid == 0) { g_thresh[b] = prefix << (64 - 8 * npass); g_cnt[b] = 0; }
}

// ----------------- band: zero flags/counts, mark banded pixels, compact list ---------------
__global__ void k_zeroflag(int P) {
    int id = blockIdx.x * 256 + threadIdx.x;
    if (id < NB * P) g_pxflag[id] = 0;
    if (id < NB) g_pxcnt[id] = 0;
}
__global__ void k_bandmark(int L, int P) {
    int id = blockIdx.x * 256 + threadIdx.x;
    if (id >= NB * L) return;
    int n = id / L, i = id - n * L;
    if (g_keys[(size_t)n * L + i] >= g_thresh[n]) g_pxflag[n * P + i / 3] = 1;
}
__global__ void k_pxcompact(int P) {
    int id = blockIdx.x * 256 + threadIdx.x;
    if (id >= NB * P) return;
    int n = id / P, px = id - n * P;
    if (g_pxflag[id]) {
        int pos = atomicAdd(&g_pxcnt[n], 1);
        if (pos < PXCAP) g_px[n * PXCAP + pos] = px;
    }
}

// ----------------- EXACT: gather conv (canonical fmaf chain) + fused 15-ch head ------------
__global__ __launch_bounds__(256)
void k_econv(const float* __restrict__ x, const float* __restrict__ bconv,
             const float* __restrict__ wobj, const float* __restrict__ bobj,
             const float* __restrict__ wdel, const float* __restrict__ bdel,
             int S, int logS, int L) {
    const int P = S * S;
    const int b = blockIdx.y;
    int cnt = g_pxcnt[b];
    int base = blockIdx.x * GPX;
    if (base >= cnt) return;
    int tid = threadIdx.x;

    __shared__ float w15s[15 * 256];
    __shared__ float b15[15];
    __shared__ __align__(16) float pool[32 * 9 * GPX];   // reused as srt[16][257]
    __shared__ int spx[GPX], spy[GPX], spxc[GPX];

    for (int i = tid; i < 3 * 256; i += 256) w15s[i] = wobj[i];
    for (int i = tid; i < 12 * 256; i += 256) w15s[768 + i] = wdel[i];
    if (tid < 3) b15[tid] = bobj[tid];
    else if (tid < 15) b15[tid] = bdel[tid - 3];

    int npx = cnt - base; if (npx > GPX) npx = GPX;
    if (tid < GPX) {
        int p = (tid < npx) ? g_px[b * PXCAP + base + tid] : 0;
        spx[tid] = p; spy[tid] = p >> logS; spxc[tid] = p & (S - 1);
    }
    __syncthreads();

    float acc[GPX];
#pragma unroll
    for (int j = 0; j < GPX; j++) acc[j] = 0.f;
    const float* xin = x + (size_t)b * 256 * P;

    for (int icb = 0; icb < 256; icb += 32) {
        for (int idx = tid; idx < 32 * 9 * GPX; idx += 256) {
            int px = idx & (GPX - 1);
            int r = idx >> 4;
            int icL = r / 9, tap = r - icL * 9;
            int t3 = tap / 3;
            int dy = t3 - 1, dx = tap - t3 * 3 - 1;
            int yy = spy[px] + dy, xx = spxc[px] + dx;
            float v = 0.f;
            if ((uint)yy < (uint)S && (uint)xx < (uint)S)
                v = xin[(size_t)(icb + icL) * P + yy * S + xx];
            pool[idx] = v;
        }
        __syncthreads();
        for (int icL = 0; icL < 32; icL++) {
#pragma unroll
            for (int tap = 0; tap < 9; tap++) {
                float w = g_wt[(size_t)((icb + icL) * 9 + tap) * 256 + tid];
                const float* sp = &pool[(icL * 9 + tap) * GPX];
                float4 v0 = *(const float4*)(sp);
                float4 v1 = *(const float4*)(sp + 4);
                float4 v2 = *(const float4*)(sp + 8);
                float4 v3 = *(const float4*)(sp + 12);
                acc[0]  = fmaf(w, v0.x, acc[0]);  acc[1]  = fmaf(w, v0.y, acc[1]);
                acc[2]  = fmaf(w, v0.z, acc[2]);  acc[3]  = fmaf(w, v0.w, acc[3]);
                acc[4]  = fmaf(w, v1.x, acc[4]);  acc[5]  = fmaf(w, v1.y, acc[5]);
                acc[6]  = fmaf(w, v1.z, acc[6]);  acc[7]  = fmaf(w, v1.w, acc[7]);
                acc[8]  = fmaf(w, v2.x, acc[8]);  acc[9]  = fmaf(w, v2.y, acc[9]);
                acc[10] = fmaf(w, v2.z, acc[10]); acc[11] = fmaf(w, v2.w, acc[11]);
                acc[12] = fmaf(w, v3.x, acc[12]); acc[13] = fmaf(w, v3.y, acc[13]);
                acc[14] = fmaf(w, v3.z, acc[14]); acc[15] = fmaf(w, v3.w, acc[15]);
            }
        }
        __syncthreads();
    }

    float bsc = bconv[tid];
#pragma unroll
    for (int px = 0; px < GPX; px++)
        pool[px * 257 + tid] = fmaxf(__fadd_rn(acc[px], bsc), 0.f);
    __syncthreads();

    if (tid < 15 * GPX) {
        int px = tid / 15, cch = tid - px * 15;
        if (px < npx) {
            float s = 0.f;
            const float* wr = &w15s[cch * 256];
            const float* tr = &pool[px * 257];
            for (int oc = 0; oc < 256; oc++) s = fmaf(wr[oc], tr[oc], s);
            s = __fadd_rn(s, b15[cch]);
            int cell = spx[px];
            if (cch < 3) {
                int i = cell * 3 + cch;
                g_bkeys[b * BKCAP + (base + px) * 3 + cch] =
                    ((ull)f2ord(s) << 32) | (uint)(~(uint)i);
            } else {
                int a = (cch - 3) >> 2, comp = (cch - 3) & 3;
                g_deltas[((size_t)b * L + cell * 3 + a) * 4 + comp] = s;
            }
        }
    }
}

// ----------------- compact exact top-k from band keys -----------------
__global__ void k_compactb() {
    int b = blockIdx.y;
    int Lb = 3 * g_pxcnt[b];
    int i = blockIdx.x * 256 + threadIdx.x;
    if (i >= Lb) return;
    ull key = g_bkeys[b * BKCAP + i];
    if (key >= g_thresh[b]) {
        int pos = atomicAdd(&g_cnt[b], 1);
        g_sel[b * 1024 + pos] = key;
    }
}

// ----------------- bitonic sort (desc) + decode (unfused _rn arithmetic) -------------------
__global__ void k_sortdecode(int W, int logW, int stride, float size,
                             int lvl, int k, int off, int L) {
    __shared__ ull skey[1024];
    int b = blockIdx.x;
    int tid = threadIdx.x;
    skey[tid] = (tid < k) ? g_sel[b * 1024 + tid] : 0ull;
    __syncthreads();
    for (int len = 2; len <= 1024; len <<= 1)
        for (int j = len >> 1; j > 0; j >>= 1) {
            int ixj = tid ^ j;
            if (ixj > tid) {
                bool desc = ((tid & len) == 0);
                ull a = skey[tid], c = skey[ixj];
                bool sw = desc ? (a < c) : (a > c);
                if (sw) { skey[tid] = c; skey[ixj] = a; }
            }
            __syncthreads();
        }
    if (tid < k) {
        ull key = skey[tid];
        uint idx = ~(uint)key;
        float s = ord2f((uint)(key >> 32));
        int a = idx % 3;
        int cell = idx / 3;
        int hy = cell >> logW, wx = cell & (W - 1);
        float ratio = (a == 0) ? 0.5f : (a == 1) ? 1.0f : 2.0f;
        float ws = __fdiv_rn(size, __fsqrt_rn(ratio));
        float hs = __fmul_rn(ws, ratio);
        float hws = __fmul_rn(0.5f, ws), hhs = __fmul_rn(0.5f, hs);
        float shx = (float)(wx * stride), shy = (float)(hy * stride);
        float ax1 = __fadd_rn(shx, -hws), ay1 = __fadd_rn(shy, -hhs);
        float ax2 = __fadd_rn(shx, hws),  ay2 = __fadd_rn(shy, hhs);
        const float* d = g_deltas + ((size_t)b * L + idx) * 4;
        float dxv = d[0], dyv = d[1];
        float dw = fminf(d[2], SC_CLAMP), dh = fminf(d[3], SC_CLAMP);
        float aw = __fsub_rn(ax2, ax1), ah = __fsub_rn(ay2, ay1);
        float cx = __fadd_rn(ax1, __fmul_rn(0.5f, aw));
        float cy = __fadd_rn(ay1, __fmul_rn(0.5f, ah));
        float pcx = __fadd_rn(__fmul_rn(dxv, aw), cx);
        float pcy = __fadd_rn(__fmul_rn(dyv, ah), cy);
        float ew = (float)exp((double)dw);
        float eh = (float)exp((double)dh);
        float pw = __fmul_rn(ew, aw), ph = __fmul_rn(eh, ah);
        float hpw = __fmul_rn(0.5f, pw), hph = __fmul_rn(0.5f, ph);
        float x1 = __fsub_rn(pcx, hpw), y1 = __fsub_rn(pcy, hph);
        float x2 = __fadd_rn(pcx, hpw), y2 = __fadd_rn(pcy, hph);
        x1 = fminf(fmaxf(x1, 0.f), 1024.f);
        y1 = fminf(fmaxf(y1, 0.f), 1024.f);
        x2 = fminf(fmaxf(x2, 0.f), 1024.f);
        y2 = fminf(fmaxf(y2, 0.f), 1024.f);
        int valid = (__fsub_rn(x2, x1) > 0.f) && (__fsub_rn(y2, y1) > 0.f);
        int ci = off + tid;
        float lo = (float)lvl * 4096.0f;
        g_cscore[b * MTOT + ci] = s;
        g_cbox[b * MTOT + ci] = make_float4(x1, y1, x2, y2);
        g_cobox[b * MTOT + ci] = make_float4(__fadd_rn(x1, lo), __fadd_rn(y1, lo),
                                             __fadd_rn(x2, lo), __fadd_rn(y2, lo));
        g_cvalid[b * MTOT + ci] = valid;
        g_gkey[b * MTOT + ci] = ((ull)(uint)(key >> 32) << 32) | (uint)(~(uint)ci);
    }
}

// ----------------- global rank via merge of 5 sorted lists -----------------
__global__ void k_rank() {
    int b = blockIdx.y;
    int ci = blockIdx.x * 256 + threadIdx.x;
    if (ci >= MTOT) return;
    const int off[6] = {0, 1000, 2000, 3000, 4000, MTOT};
    ull key = g_gkey[b * MTOT + ci];
    int l = ci / 1000; if (l > 4) l = 4;
    int rank = ci - off[l];
    for (int o = 0; o < 5; o++) {
        if (o == l) continue;
        int lo = off[o], hi = off[o + 1];
        while (lo < hi) {
            int mid = (lo + hi) >> 1;
            if (g_gkey[b * MTOT + mid] > key) lo = mid + 1; else hi = mid;
        }
        rank += lo - off[o];
    }
    g_order[b * MTOT + rank] = ci;
}

// ----------------- NMS suppression bitmasks (unfused _rn IoU) -----------------
__global__ void k_mask() {
    int b = blockIdx.z;
    int l = blockIdx.y;
    int k = (l == 4) ? 768 : 1000;
    int i = blockIdx.x * 8 + threadIdx.y;
    int w = threadIdx.x;
    if (i >= k) return;
    int off = l * 1000;
    float4 A = g_cobox[b * MTOT + off + i];
    float areaA = __fmul_rn(__fsub_rn(A.z, A.x), __fsub_rn(A.w, A.y));
    ull word = 0;
    int jmax = i - w * 64; if (jmax > 64) jmax = 64;
    for (int t = 0; t < jmax; t++) {
        int j = w * 64 + t;
        float4 B = g_cobox[b * MTOT + off + j];
        float areaB = __fmul_rn(__fsub_rn(B.z, B.x), __fsub_rn(B.w, B.y));
        float ltx = fmaxf(A.x, B.x), lty = fmaxf(A.y, B.y);
        float rbx = fminf(A.z, B.z), rby = fminf(A.w, B.w);
        float iw = fmaxf(__fsub_rn(rbx, ltx), 0.f);
        float ih = fmaxf(__fsub_rn(rby, lty), 0.f);
        float inter = __fmul_rn(iw, ih);
        float denom = __fadd_rn(__fsub_rn(__fadd_rn(areaA, areaB), inter), 1e-9f);
        float iou = __fdiv_rn(inter, denom);
        if (iou > 0.7f) word |= 1ull << t;
    }
    g_mask[((size_t)(b * 5 + l) * 1000 + i) * 16 + w] = word;
}

// ----------------- serial greedy NMS scan (1 warp per batch-level) -----------------
__global__ void k_nms() {
    int b = blockIdx.y, l = blockIdx.x;
    int k = (l == 4) ? 768 : 1000;
    int off = l * 1000;
    int lane = threadIdx.x;
    const ull* mbase = g_mask + (size_t)(b * 5 + l) * 1000 * 16;
    ull keepw = 0;
    ull row = (lane < 16) ? mbase[lane] : 0;
    for (int i = 0; i < k; i++) {
        ull nrow = (lane < 16 && i + 1 < k) ? mbase[(size_t)(i + 1) * 16 + lane] : 0;
        bool sup = __any_sync(0xFFFFFFFFu, (row & keepw) != 0);
        int vi = g_cvalid[b * MTOT + off + i];
        int ki = (vi && !sup) ? 1 : 0;
        if (ki && lane == (i >> 6)) keepw |= 1ull << (i & 63);
        if (lane == 0) g_keep[b * MTOT + off + i] = ki;
        row = nrow;
    }
}

// ----------------- stable partition + output -----------------
__global__ void k_out(float* __restrict__ out) {
    __shared__ int flag[MTOT];
    __shared__ int part[1024];
    __shared__ int sK;
    int b = blockIdx.x;
    int tid = threadIdx.x;
    for (int r = tid; r < MTOT; r += 1024)
        flag[r] = g_keep[b * MTOT + g_order[b * MTOT + r]];
    __syncthreads();
    int base = tid * 5;
    int mysum = 0;
#pragma unroll
    for (int j = 0; j < 5; j++) {
        int r = base + j;
        if (r < MTOT) mysum += flag[r];
    }
    part[tid] = mysum;
    __syncthreads();
    for (int d = 1; d < 1024; d <<= 1) {
        int v = (tid >= d) ? part[tid - d] : 0;
        __syncthreads();
        part[tid] += v;
        __syncthreads();
    }
    if (tid == 1023) sK = part[1023];
    __syncthreads();
    int run = part[tid] - mysum;
    int Ktot = sK;
    for (int j = 0; j < 5; j++) {
        int r = base + j;
        if (r >= MTOT) break;
        int ci = g_order[b * MTOT + r];
        int f = flag[r];
        int pos;
        float sc;
        if (f) { pos = run; sc = g_cscore[b * MTOT + ci]; }
        else   { pos = Ktot + (r - run); sc = NEG_S; }
        run += f;
        if (pos < 1000) {
            float4 bx = g_cbox[b * MTOT + ci];
            float* o = out + ((size_t)b * 1000 + pos) * 5;
            o[0] = bx.x; o[1] = bx.y; o[2] = bx.z; o[3] = bx.w; o[4] = sc;
        }
    }
}

// ----------------- launch -----------------
extern "C" void kernel_launch(void* const* d_in, const int* in_sizes, int n_in,
                              void* d_out, int out_size) {
    const float* feats[5] = {(const float*)d_in[0], (const float*)d_in[1],
                             (const float*)d_in[2], (const float*)d_in[3],
                             (const float*)d_in[4]};
    const float* w_conv  = (const float*)d_in[5];
    const float* b_conv  = (const float*)d_in[6];
    const float* w_obj   = (const float*)d_in[7];
    const float* b_obj   = (const float*)d_in[8];
    const float* w_delta = (const float*)d_in[9];
    const float* b_delta = (const float*)d_in[10];
    float* out = (float*)d_out;

    const int   Ss[5]  = {256, 128, 64, 32, 16};
    const int   LG[5]  = {8, 7, 6, 5, 4};
    const int   STm[5] = {4, 8, 16, 32, 64};
    const float SZ[5]  = {32.f, 64.f, 128.f, 256.f, 512.f};
    const int   KL[5]  = {1000, 1000, 1000, 1000, 768};
    const int   OFF[5] = {0, 1000, 2000, 3000, 4000};

    cudaFuncSetAttribute(k_tconv, cudaFuncAttributeMaxDynamicSharedMemorySize, TDYN);

    k_transpose_w<<<2304, 256>>>(w_conv);

    for (int l = 0; l < 5; l++) {
        int S = Ss[l], P = S * S, L = P * 3;
        int Bb = (BBAND < L) ? BBAND : L;
        int logC = (S >= 32) ? 5 : 4;
        // phase A: halo-tiled fp16 MMA conv + fused objectness -> approx keys
        k_tconv<<<dim3(P / 128, NB), 256, TDYN>>>(feats[l], b_conv, w_obj, b_obj, S, logC, L);
        k_select<<<NB, 1024>>>(0, L, Bb, 4);               // approx band threshold (score bits)
        k_zeroflag<<<(NB * P + 255) / 256, 256>>>(P);
        k_bandmark<<<(NB * L + 255) / 256, 256>>>(L, P);
        k_pxcompact<<<(NB * P + 255) / 256, 256>>>(P);
        // phase B: exact recompute on band pixels only -> compact keys
        k_econv<<<dim3(PXCAP / GPX, NB), 256>>>(feats[l], b_conv, w_obj, b_obj,
                                                w_delta, b_delta, S, LG[l], L);
        k_select<<<NB, 1024>>>(1, 0, KL[l], 8);            // exact top-k over band keys
        k_compactb<<<dim3(BKCAP / 256, NB), 256>>>();
        k_sortdecode<<<NB, 1024>>>(S, LG[l], STm[l], SZ[l], l, KL[l], OFF[l], L);
    }

    k_rank<<<dim3((MTOT + 255) / 256, NB), 256>>>();
    k_mask<<<dim3(125, 5, NB), dim3(16, 8)>>>();
    k_nms<<<dim3(5, NB), 32>>>();
    k_out<<<NB, 1024>>>(out);
}

// round 16
// speedup vs baseline: 1.4438x; 1.0345x over previous
#include <cuda_runtime.h>
#include <cuda_fp16.h>
#include <math.h>

typedef unsigned long long ull;
typedef unsigned int uint;

#define NB 2
#define MTOT 4768
#define SC_CLAMP 4.135166556742356f
#define NEG_S -10000.0f
#define BBAND 5000
#define GPX 16
#define PXCAP 8192
#define BKCAP 24576
#define WPITCH 24
#define TDYN (2304 * WPITCH * 2 + 7344)

// ----------------- static scratch -----------------
__device__ float  g_wt[2304 * 256];                  // [k = ic*9+tap][oc] fp32
__device__ __half g_wth[2304 * 256];                 // same, fp16
__device__ __half g_wtk[16 * 9 * 256 * 16];          // [chunk][tap][oc][k16] fp16
__device__ float  g_deltas[(size_t)NB * 196608 * 4];
__device__ ull    g_keys[(size_t)NB * 196608];       // approx keys (full L)
__device__ ull    g_bkeys[NB * BKCAP];               // exact keys (compact band)
__device__ ull    g_thresh[NB];
__device__ int    g_cnt[NB];
__device__ ull    g_sel[NB * 1024];
__device__ int    g_pxflag[NB * 65536];
__device__ int    g_pxcnt[NB];
__device__ int    g_px[NB * PXCAP];
__device__ int    g_hist256[NB][256];
__device__ ull    g_pref[NB];
__device__ int    g_rem[NB];
__device__ float  g_cscore[NB * MTOT];
__device__ float4 g_cbox[NB * MTOT];
__device__ float4 g_cobox[NB * MTOT];
__device__ int    g_cvalid[NB * MTOT];
__device__ ull    g_gkey[NB * MTOT];
__device__ int    g_order[NB * MTOT];
__device__ ull    g_mask[(size_t)NB * 5 * 1000 * 16];
__device__ int    g_keep[NB * MTOT];

__device__ __forceinline__ uint f2ord(float s) {
    uint u = __float_as_uint(s);
    return (u & 0x80000000u) ? ~u : (u | 0x80000000u);
}
__device__ __forceinline__ float ord2f(uint o) {
    uint u = (o & 0x80000000u) ? (o & 0x7FFFFFFFu) : ~o;
    return __uint_as_float(u);
}

// ----------------- weight transpose: fp32 [k][oc], fp16 [k][oc], fp16 frag [chunk][tap][oc][k16]
__global__ void k_transpose_w(const float* __restrict__ w) {
    int idx = blockIdx.x * 256 + threadIdx.x;
    if (idx >= 2304 * 256) return;
    int oc = idx & 255;
    int k = idx >> 8;
    int ic = k / 9, tap = k - ic * 9;
    float v = w[(oc * 256 + ic) * 9 + tap];
    g_wt[idx] = v;
    g_wth[idx] = __float2half(v);
    int chunk = ic >> 4, kloc = ic & 15;
    g_wtk[(((chunk * 9 + tap) * 256 + oc) << 4) + kloc] = __float2half(v);
}

// ----------------- APPROX: halo-tiled fp16 MMA conv + fused objectness head ----------------
#define MMA_F16(c, a0, a1, a2, a3, b0, b1)                               \
    asm("mma.sync.aligned.m16n8k16.row.col.f32.f16.f16.f32 "             \
        "{%0,%1,%2,%3}, {%4,%5,%6,%7}, {%8,%9}, {%0,%1,%2,%3};"          \
        : "+f"(c[0]), "+f"(c[1]), "+f"(c[2]), "+f"(c[3])                 \
        : "r"(a0), "r"(a1), "r"(a2), "r"(a3), "r"(b0), "r"(b1))

__global__ __launch_bounds__(256, 1)
void k_tconv(const float* __restrict__ x, const float* __restrict__ bconv,
             const float* __restrict__ wobj, const float* __restrict__ bobj,
             int S, int logC, int L) {
    const int P = S * S;
    const int C = 1 << logC;
    const int R = 128 >> logC;
    const int Wh = C + 2;
    const int Nh = (R + 2) * Wh;
    const int b = blockIdx.y;
    const int bi = blockIdx.x;
    const int ntx = S >> logC;
    const int by0 = (bi / ntx) * R;
    const int bx0 = (bi - (bi / ntx) * ntx) * C;
    const float* xin = x + (size_t)b * 256 * P;

    extern __shared__ char dsm[];
    __half* dynW = (__half*)dsm;                     // [tap][oc][WPITCH] (110592 B)
    __half* dynA = (__half*)(dsm + 2304 * WPITCH * 2); // [halo px][18]   (7344 B)
    __half (*sT)[264] = (__half(*)[264])dsm;         // epilogue reuse

    __shared__ float sWo[768];
    __shared__ float sBias[256];
    __shared__ float sBo[3];

    const int tid = threadIdx.x;
    const int lane = tid & 31;
    const int wid = tid >> 5;
    const int qid = lane >> 2;
    const int qt = lane & 3;
    const int pxb = (wid & 3) * 32;
    const int ocb = (wid >> 2) * 128;

    for (int i = tid; i < 768; i += 256) sWo[i] = wobj[i];
    if (tid < 256) sBias[tid] = bconv[tid];
    if (tid < 3) sBo[tid] = bobj[tid];

    int rb[2][2];
#pragma unroll
    for (int m = 0; m < 2; m++) {
        int lp0 = pxb + m * 16 + qid;
        int lp1 = lp0 + 8;
        rb[m][0] = (lp0 >> logC) * Wh + (lp0 & (C - 1));
        rb[m][1] = (lp1 >> logC) * Wh + (lp1 & (C - 1));
    }

    float c[2][16][4];
#pragma unroll
    for (int m = 0; m < 2; m++)
#pragma unroll
        for (int n = 0; n < 16; n++)
#pragma unroll
            for (int r = 0; r < 4; r++) c[m][n][r] = 0.f;

    for (int icb = 0; icb < 256; icb += 16) {
        // stage weights: 2304 rows of 16 halves (32B) -> pitch WPITCH; uint4 coalesced
        const __half* wsrc = g_wtk + (size_t)(icb >> 4) * 9 * 256 * 16;
        for (int idx = tid; idx < 4608; idx += 256) {
            int r = idx >> 1, h = idx & 1;
            uint4 v = *(const uint4*)(wsrc + (r << 4) + h * 8);
            *(uint4*)(dynW + r * WPITCH + h * 8) = v;
        }
        // stage input halo: [halo px][16 ic], zero-padded at image borders
        for (int idx = tid; idx < 16 * Nh; idx += 256) {
            int i = idx / Nh, h = idx - i * Nh;
            int hy = h / Wh, hx = h - hy * Wh;
            int gy = by0 + hy - 1, gx = bx0 + hx - 1;
            float v = ((uint)gy < (uint)S && (uint)gx < (uint)S)
                          ? xin[(size_t)(icb + i) * P + gy * S + gx] : 0.f;
            dynA[h * 18 + i] = __float2half(v);
        }
        __syncthreads();
#pragma unroll
        for (int tap = 0; tap < 9; tap++) {
            const int t3 = tap / 3;
            const int to = t3 * Wh + (tap - 3 * t3);   // (dy+1)*Wh + (dx+1)
            uint a[2][4];
#pragma unroll
            for (int m = 0; m < 2; m++) {
                const __half* p0 = dynA + (rb[m][0] + to) * 18;
                const __half* p1 = dynA + (rb[m][1] + to) * 18;
                a[m][0] = *(const uint*)(p0 + 2 * qt);
                a[m][1] = *(const uint*)(p1 + 2 * qt);
                a[m][2] = *(const uint*)(p0 + 2 * qt + 8);
                a[m][3] = *(const uint*)(p1 + 2 * qt + 8);
            }
            const __half* wt = dynW + tap * 256 * WPITCH;
#pragma unroll
            for (int n = 0; n < 16; n++) {
                const __half* bp = wt + (ocb + n * 8 + qid) * WPITCH + 2 * qt;
                uint b0 = *(const uint*)bp;
                uint b1 = *(const uint*)(bp + 8);
                MMA_F16(c[0][n], a[0][0], a[0][1], a[0][2], a[0][3], b0, b1);
                MMA_F16(c[1][n], a[1][0], a[1][1], a[1][2], a[1][3], b0, b1);
            }
        }
        __syncthreads();
    }

    // epilogue: bias + relu -> half sT[px][oc] (reuses dyn smem)
#pragma unroll
    for (int m = 0; m < 2; m++)
#pragma unroll
        for (int n = 0; n < 16; n++) {
            int pxl = pxb + m * 16 + qid;
            int oc = ocb + n * 8 + 2 * qt;
            float t0 = fmaxf(c[m][n][0] + sBias[oc], 0.f);
            float t1 = fmaxf(c[m][n][1] + sBias[oc + 1], 0.f);
            *(__half2*)&sT[pxl][oc] = __floats2half2_rn(t0, t1);
            float t2 = fmaxf(c[m][n][2] + sBias[oc], 0.f);
            float t3v = fmaxf(c[m][n][3] + sBias[oc + 1], 0.f);
            *(__half2*)&sT[pxl + 8][oc] = __floats2half2_rn(t2, t3v);
        }
    __syncthreads();

    // fused approx objectness head: 128 px x 3 anchors
    for (int idx = tid; idx < 384; idx += 256) {
        int lp = idx / 3, a = idx - lp * 3;
        const float* wr_ = &sWo[a * 256];
        float s = 0.f;
        for (int oc = 0; oc < 256; oc++)
            s = fmaf(wr_[oc], __half2float(sT[lp][oc]), s);
        s += sBo[a];
        int g = (by0 + (lp >> logC)) * S + bx0 + (lp & (C - 1));
        int i = g * 3 + a;
        g_keys[(size_t)b * L + i] = ((ull)f2ord(s) << 32) | (uint)(~(uint)i);
    }
}

// ----------------- multi-block exact radix select (approx band, large L) -------------------
__global__ void k_selinit(int k) {
    int b = blockIdx.x;
    if (threadIdx.x < 256) g_hist256[b][threadIdx.x] = 0;
    if (threadIdx.x == 0) { g_pref[b] = 0; g_rem[b] = k; }
}
__global__ void k_hist(int L, int pass) {
    int b = blockIdx.y;
    __shared__ int h[256];
    if (threadIdx.x < 256) h[threadIdx.x] = 0;
    __syncthreads();
    ull prefix = g_pref[b];
    int bsh = 56 - 8 * pass;
    const ull* keys = g_keys + (size_t)b * L;
    for (int i = blockIdx.x * 256 + threadIdx.x; i < L; i += gridDim.x * 256) {
        ull key = keys[i];
        bool m = (pass == 0) || ((key >> (64 - 8 * pass)) == prefix);
        if (m) atomicAdd(&h[(int)((key >> bsh) & 255)], 1);
    }
    __syncthreads();
    if (threadIdx.x < 256 && h[threadIdx.x])
        atomicAdd(&g_hist256[b][threadIdx.x], h[threadIdx.x]);
}
__global__ void k_pick(int pass, int npass) {
    int b = blockIdx.x;
    if (threadIdx.x == 0) {
        int r = g_rem[b], acc = 0, byte = 0;
        for (int v = 255; v >= 0; v--) {
            int hv = g_hist256[b][v];
            if (acc + hv >= r) { byte = v; break; }
            acc += hv;
        }
        g_pref[b] = (g_pref[b] << 8) | (uint)byte;
        g_rem[b] = r - acc;
        if (pass == npass - 1) { g_thresh[b] = g_pref[b] << (64 - 8 * npass); g_cnt[b] = 0; }
    }
    __syncthreads();
    for (int i = threadIdx.x; i < 256; i += blockDim.x) g_hist256[b][i] = 0;
}

// ----------------- single-block radix-select (small L / band keys) -------------------------
__global__ void k_select(int src, int Lfix, int k, int npass) {
    __shared__ int hist[256];
    __shared__ ull sprefix;
    __shared__ int sr;
    int b = blockIdx.x;
    int tid = threadIdx.x;
    const ull* keys;
    int L;
    if (src == 0) { keys = g_keys + (size_t)b * Lfix; L = Lfix; }
    else          { keys = g_bkeys + b * BKCAP;       L = 3 * g_pxcnt[b]; }
    ull prefix = 0;
    int r = k;
    for (int pass = 0; pass < npass; pass++) {
        if (tid < 256) hist[tid] = 0;
        __syncthreads();
        int bsh = 56 - 8 * pass;
        for (int i = tid; i < L; i += 1024) {
            ull key = keys[i];
            bool m = (pass == 0) || ((key >> (64 - 8 * pass)) == prefix);
            if (m) atomicAdd(&hist[(int)((key >> bsh) & 255)], 1);
        }
        __syncthreads();
        if (tid == 0) {
            int acc = 0, byte = 0;
            for (int v = 255; v >= 0; v--) {
                if (acc + hist[v] >= r) { byte = v; break; }
                acc += hist[v];
            }
            sprefix = (prefix << 8) | (uint)byte;
            sr = r - acc;
        }
        __syncthreads();
        prefix = sprefix;
        r = sr;
        __syncthreads();
    }
    if (tid == 0) { g_thresh[b] = prefix << (64 - 8 * npass); g_cnt[b] = 0; }
}

// ----------------- band: zero flags/counts, mark banded pixels, compact list ---------------
__global__ void k_zeroflag(int P) {
    int id = blockIdx.x * 256 + threadIdx.x;
    if (id < NB * P) g_pxflag[id] = 0;
    if (id < NB) g_pxcnt[id] = 0;
}
__global__ void k_bandmark(int L, int P) {
    int id = blockIdx.x * 256 + threadIdx.x;
    if (id >= NB * L) return;
    int n = id / L, i = id - n * L;
    if (g_keys[(size_t)n * L + i] >= g_thresh[n]) g_pxflag[n * P + i / 3] = 1;
}
__global__ void k_pxcompact(int P) {
    int id = blockIdx.x * 256 + threadIdx.x;
    if (id >= NB * P) return;
    int n = id / P, px = id - n * P;
    if (g_pxflag[id]) {
        int pos = atomicAdd(&g_pxcnt[n], 1);
        if (pos < PXCAP) g_px[n * PXCAP + pos] = px;
    }
}

// ----------------- EXACT: gather conv (canonical fmaf chain) + fused 15-ch head ------------
__global__ __launch_bounds__(256)
void k_econv(const float* __restrict__ x, const float* __restrict__ bconv,
             const float* __restrict__ wobj, const float* __restrict__ bobj,
             const float* __restrict__ wdel, const float* __restrict__ bdel,
             int S, int logS, int L) {
    const int P = S * S;
    const int b = blockIdx.y;
    int cnt = g_pxcnt[b];
    int base = blockIdx.x * GPX;
    if (base >= cnt) return;
    int tid = threadIdx.x;

    __shared__ float w15s[15 * 256];
    __shared__ float b15[15];
    __shared__ __align__(16) float pool[32 * 9 * GPX];   // reused as srt[16][257]
    __shared__ int spx[GPX], spy[GPX], spxc[GPX];

    for (int i = tid; i < 3 * 256; i += 256) w15s[i] = wobj[i];
    for (int i = tid; i < 12 * 256; i += 256) w15s[768 + i] = wdel[i];
    if (tid < 3) b15[tid] = bobj[tid];
    else if (tid < 15) b15[tid] = bdel[tid - 3];

    int npx = cnt - base; if (npx > GPX) npx = GPX;
    if (tid < GPX) {
        int p = (tid < npx) ? g_px[b * PXCAP + base + tid] : 0;
        spx[tid] = p; spy[tid] = p >> logS; spxc[tid] = p & (S - 1);
    }
    __syncthreads();

    float acc[GPX];
#pragma unroll
    for (int j = 0; j < GPX; j++) acc[j] = 0.f;
    const float* xin = x + (size_t)b * 256 * P;

    for (int icb = 0; icb < 256; icb += 32) {
        for (int idx = tid; idx < 32 * 9 * GPX; idx += 256) {
            int px = idx & (GPX - 1);
            int r = idx >> 4;
            int icL = r / 9, tap = r - icL * 9;
            int t3 = tap / 3;
            int dy = t3 - 1, dx = tap - t3 * 3 - 1;
            int yy = spy[px] + dy, xx = spxc[px] + dx;
            float v = 0.f;
            if ((uint)yy < (uint)S && (uint)xx < (uint)S)
                v = xin[(size_t)(icb + icL) * P + yy * S + xx];
            pool[idx] = v;
        }
        __syncthreads();
        for (int icL = 0; icL < 32; icL++) {
#pragma unroll
            for (int tap = 0; tap < 9; tap++) {
                float w = g_wt[(size_t)((icb + icL) * 9 + tap) * 256 + tid];
                const float* sp = &pool[(icL * 9 + tap) * GPX];
                float4 v0 = *(const float4*)(sp);
                float4 v1 = *(const float4*)(sp + 4);
                float4 v2 = *(const float4*)(sp + 8);
                float4 v3 = *(const float4*)(sp + 12);
                acc[0]  = fmaf(w, v0.x, acc[0]);  acc[1]  = fmaf(w, v0.y, acc[1]);
                acc[2]  = fmaf(w, v0.z, acc[2]);  acc[3]  = fmaf(w, v0.w, acc[3]);
                acc[4]  = fmaf(w, v1.x, acc[4]);  acc[5]  = fmaf(w, v1.y, acc[5]);
                acc[6]  = fmaf(w, v1.z, acc[6]);  acc[7]  = fmaf(w, v1.w, acc[7]);
                acc[8]  = fmaf(w, v2.x, acc[8]);  acc[9]  = fmaf(w, v2.y, acc[9]);
                acc[10] = fmaf(w, v2.z, acc[10]); acc[11] = fmaf(w, v2.w, acc[11]);
                acc[12] = fmaf(w, v3.x, acc[12]); acc[13] = fmaf(w, v3.y, acc[13]);
                acc[14] = fmaf(w, v3.z, acc[14]); acc[15] = fmaf(w, v3.w, acc[15]);
            }
        }
        __syncthreads();
    }

    float bsc = bconv[tid];
#pragma unroll
    for (int px = 0; px < GPX; px++)
        pool[px * 257 + tid] = fmaxf(__fadd_rn(acc[px], bsc), 0.f);
    __syncthreads();

    if (tid < 15 * GPX) {
        int px = tid / 15, cch = tid - px * 15;
        if (px < npx) {
            float s = 0.f;
            const float* wr = &w15s[cch * 256];
            const float* tr = &pool[px * 257];
            for (int oc = 0; oc < 256; oc++) s = fmaf(wr[oc], tr[oc], s);
            s = __fadd_rn(s, b15[cch]);
            int cell = spx[px];
            if (cch < 3) {
                int i = cell * 3 + cch;
                g_bkeys[b * BKCAP + (base + px) * 3 + cch] =
                    ((ull)f2ord(s) << 32) | (uint)(~(uint)i);
            } else {
                int a = (cch - 3) >> 2, comp = (cch - 3) & 3;
                g_deltas[((size_t)b * L + cell * 3 + a) * 4 + comp] = s;
            }
        }
    }
}

// ----------------- compact exact top-k from band keys -----------------
__global__ void k_compactb() {
    int b = blockIdx.y;
    int Lb = 3 * g_pxcnt[b];
    int i = blockIdx.x * 256 + threadIdx.x;
    if (i >= Lb) return;
    ull key = g_bkeys[b * BKCAP + i];
    if (key >= g_thresh[b]) {
        int pos = atomicAdd(&g_cnt[b], 1);
        g_sel[b * 1024 + pos] = key;
    }
}

// ----------------- bitonic sort (desc) + decode (unfused _rn arithmetic) -------------------
__global__ void k_sortdecode(int W, int logW, int stride, float size,
                             int lvl, int k, int off, int L) {
    __shared__ ull skey[1024];
    int b = blockIdx.x;
    int tid = threadIdx.x;
    skey[tid] = (tid < k) ? g_sel[b * 1024 + tid] : 0ull;
    __syncthreads();
    for (int len = 2; len <= 1024; len <<= 1)
        for (int j = len >> 1; j > 0; j >>= 1) {
            int ixj = tid ^ j;
            if (ixj > tid) {
                bool desc = ((tid & len) == 0);
                ull a = skey[tid], c = skey[ixj];
                bool sw = desc ? (a < c) : (a > c);
                if (sw) { skey[tid] = c; skey[ixj] = a; }
            }
            __syncthreads();
        }
    if (tid < k) {
        ull key = skey[tid];
        uint idx = ~(uint)key;
        float s = ord2f((uint)(key >> 32));
        int a = idx % 3;
        int cell = idx / 3;
        int hy = cell >> logW, wx = cell & (W - 1);
        float ratio = (a == 0) ? 0.5f : (a == 1) ? 1.0f : 2.0f;
        float ws = __fdiv_rn(size, __fsqrt_rn(ratio));
        float hs = __fmul_rn(ws, ratio);
        float hws = __fmul_rn(0.5f, ws), hhs = __fmul_rn(0.5f, hs);
        float shx = (float)(wx * stride), shy = (float)(hy * stride);
        float ax1 = __fadd_rn(shx, -hws), ay1 = __fadd_rn(shy, -hhs);
        float ax2 = __fadd_rn(shx, hws),  ay2 = __fadd_rn(shy, hhs);
        const float* d = g_deltas + ((size_t)b * L + idx) * 4;
        float dxv = d[0], dyv = d[1];
        float dw = fminf(d[2], SC_CLAMP), dh = fminf(d[3], SC_CLAMP);
        float aw = __fsub_rn(ax2, ax1), ah = __fsub_rn(ay2, ay1);
        float cx = __fadd_rn(ax1, __fmul_rn(0.5f, aw));
        float cy = __fadd_rn(ay1, __fmul_rn(0.5f, ah));
        float pcx = __fadd_rn(__fmul_rn(dxv, aw), cx);
        float pcy = __fadd_rn(__fmul_rn(dyv, ah), cy);
        float ew = (float)exp((double)dw);
        float eh = (float)exp((double)dh);
        float pw = __fmul_rn(ew, aw), ph = __fmul_rn(eh, ah);
        float hpw = __fmul_rn(0.5f, pw), hph = __fmul_rn(0.5f, ph);
        float x1 = __fsub_rn(pcx, hpw), y1 = __fsub_rn(pcy, hph);
        float x2 = __fadd_rn(pcx, hpw), y2 = __fadd_rn(pcy, hph);
        x1 = fminf(fmaxf(x1, 0.f), 1024.f);
        y1 = fminf(fmaxf(y1, 0.f), 1024.f);
        x2 = fminf(fmaxf(x2, 0.f), 1024.f);
        y2 = fminf(fmaxf(y2, 0.f), 1024.f);
        int valid = (__fsub_rn(x2, x1) > 0.f) && (__fsub_rn(y2, y1) > 0.f);
        int ci = off + tid;
        float lo = (float)lvl * 4096.0f;
        g_cscore[b * MTOT + ci] = s;
        g_cbox[b * MTOT + ci] = make_float4(x1, y1, x2, y2);
        g_cobox[b * MTOT + ci] = make_float4(__fadd_rn(x1, lo), __fadd_rn(y1, lo),
                                             __fadd_rn(x2, lo), __fadd_rn(y2, lo));
        g_cvalid[b * MTOT + ci] = valid;
        g_gkey[b * MTOT + ci] = ((ull)(uint)(key >> 32) << 32) | (uint)(~(uint)ci);
    }
}

// ----------------- global rank via merge of 5 sorted lists -----------------
__global__ void k_rank() {
    int b = blockIdx.y;
    int ci = blockIdx.x * 256 + threadIdx.x;
    if (ci >= MTOT) return;
    const int off[6] = {0, 1000, 2000, 3000, 4000, MTOT};
    ull key = g_gkey[b * MTOT + ci];
    int l = ci / 1000; if (l > 4) l = 4;
    int rank = ci - off[l];
    for (int o = 0; o < 5; o++) {
        if (o == l) continue;
        int lo = off[o], hi = off[o + 1];
        while (lo < hi) {
            int mid = (lo + hi) >> 1;
            if (g_gkey[b * MTOT + mid] > key) lo = mid + 1; else hi = mid;
        }
        rank += lo - off[o];
    }
    g_order[b * MTOT + rank] = ci;
}

// ----------------- NMS suppression bitmasks (unfused _rn IoU) -----------------
__global__ void k_mask() {
    int b = blockIdx.z;
    int l = blockIdx.y;
    int k = (l == 4) ? 768 : 1000;
    int i = blockIdx.x * 8 + threadIdx.y;
    int w = threadIdx.x;
    if (i >= k) return;
    int off = l * 1000;
    float4 A = g_cobox[b * MTOT + off + i];
    float areaA = __fmul_rn(__fsub_rn(A.z, A.x), __fsub_rn(A.w, A.y));
    ull word = 0;
    int jmax = i - w * 64; if (jmax > 64) jmax = 64;
    for (int t = 0; t < jmax; t++) {
        int j = w * 64 + t;
        float4 B = g_cobox[b * MTOT + off + j];
        float areaB = __fmul_rn(__fsub_rn(B.z, B.x), __fsub_rn(B.w, B.y));
        float ltx = fmaxf(A.x, B.x), lty = fmaxf(A.y, B.y);
        float rbx = fminf(A.z, B.z), rby = fminf(A.w, B.w);
        float iw = fmaxf(__fsub_rn(rbx, ltx), 0.f);
        float ih = fmaxf(__fsub_rn(rby, lty), 0.f);
        float inter = __fmul_rn(iw, ih);
        float denom = __fadd_rn(__fsub_rn(__fadd_rn(areaA, areaB), inter), 1e-9f);
        float iou = __fdiv_rn(inter, denom);
        if (iou > 0.7f) word |= 1ull << t;
    }
    g_mask[((size_t)(b * 5 + l) * 1000 + i) * 16 + w] = word;
}

// ----------------- serial greedy NMS scan (1 warp per batch-level) -----------------
__global__ void k_nms() {
    int b = blockIdx.y, l = blockIdx.x;
    int k = (l == 4) ? 768 : 1000;
    int off = l * 1000;
    int lane = threadIdx.x;
    const ull* mbase = g_mask + (size_t)(b * 5 + l) * 1000 * 16;
    ull keepw = 0;
    ull row = (lane < 16) ? mbase[lane] : 0;
    for (int i = 0; i < k; i++) {
        ull nrow = (lane < 16 && i + 1 < k) ? mbase[(size_t)(i + 1) * 16 + lane] : 0;
        bool sup = __any_sync(0xFFFFFFFFu, (row & keepw) != 0);
        int vi = g_cvalid[b * MTOT + off + i];
        int ki = (vi && !sup) ? 1 : 0;
        if (ki && lane == (i >> 6)) keepw |= 1ull << (i & 63);
        if (lane == 0) g_keep[b * MTOT + off + i] = ki;
        row = nrow;
    }
}

// ----------------- stable partition + output -----------------
__global__ void k_out(float* __restrict__ out) {
    __shared__ int flag[MTOT];
    __shared__ int part[1024];
    __shared__ int sK;
    int b = blockIdx.x;
    int tid = threadIdx.x;
    for (int r = tid; r < MTOT; r += 1024)
        flag[r] = g_keep[b * MTOT + g_order[b * MTOT + r]];
    __syncthreads();
    int base = tid * 5;
    int mysum = 0;
#pragma unroll
    for (int j = 0; j < 5; j++) {
        int r = base + j;
        if (r < MTOT) mysum += flag[r];
    }
    part[tid] = mysum;
    __syncthreads();
    for (int d = 1; d < 1024; d <<= 1) {
        int v = (tid >= d) ? part[tid - d] : 0;
        __syncthreads();
        part[tid] += v;
        __syncthreads();
    }
    if (tid == 1023) sK = part[1023];
    __syncthreads();
    int run = part[tid] - mysum;
    int Ktot = sK;
    for (int j = 0; j < 5; j++) {
        int r = base + j;
        if (r >= MTOT) break;
        int ci = g_order[b * MTOT + r];
        int f = flag[r];
        int pos;
        float sc;
        if (f) { pos = run; sc = g_cscore[b * MTOT + ci]; }
        else   { pos = Ktot + (r - run); sc = NEG_S; }
        run += f;
        if (pos < 1000) {
            float4 bx = g_cbox[b * MTOT + ci];
            float* o = out + ((size_t)b * 1000 + pos) * 5;
            o[0] = bx.x; o[1] = bx.y; o[2] = bx.z; o[3] = bx.w; o[4] = sc;
        }
    }
}

// ----------------- launch -----------------
extern "C" void kernel_launch(void* const* d_in, const int* in_sizes, int n_in,
                              void* d_out, int out_size) {
    const float* feats[5] = {(const float*)d_in[0], (const float*)d_in[1],
                             (const float*)d_in[2], (const float*)d_in[3],
                             (const float*)d_in[4]};
    const float* w_conv  = (const float*)d_in[5];
    const float* b_conv  = (const float*)d_in[6];
    const float* w_obj   = (const float*)d_in[7];
    const float* b_obj   = (const float*)d_in[8];
    const float* w_delta = (const float*)d_in[9];
    const float* b_delta = (const float*)d_in[10];
    float* out = (float*)d_out;

    const int   Ss[5]  = {256, 128, 64, 32, 16};
    const int   LG[5]  = {8, 7, 6, 5, 4};
    const int   STm[5] = {4, 8, 16, 32, 64};
    const float SZ[5]  = {32.f, 64.f, 128.f, 256.f, 512.f};
    const int   KL[5]  = {1000, 1000, 1000, 1000, 768};
    const int   OFF[5] = {0, 1000, 2000, 3000, 4000};

    cudaFuncSetAttribute(k_tconv, cudaFuncAttributeMaxDynamicSharedMemorySize, TDYN);

    k_transpose_w<<<2304, 256>>>(w_conv);

    for (int l = 0; l < 5; l++) {
        int S = Ss[l], P = S * S, L = P * 3;
        int Bb = (BBAND < L) ? BBAND : L;
        int logC = (S >= 32) ? 5 : 4;
        // phase A: halo-tiled fp16 MMA conv + fused objectness -> approx keys
        k_tconv<<<dim3(P / 128, NB), 256, TDYN>>>(feats[l], b_conv, w_obj, b_obj, S, logC, L);
        if (l < 2) {
            // multi-block exact radix select (4 score-byte passes)
            k_selinit<<<NB, 256>>>(Bb);
            for (int p = 0; p < 4; p++) {
                k_hist<<<dim3(64, NB), 256>>>(L, p);
                k_pick<<<NB, 256>>>(p, 4);
            }
        } else {
            k_select<<<NB, 1024>>>(0, L, Bb, 4);
        }
        k_zeroflag<<<(NB * P + 255) / 256, 256>>>(P);
        k_bandmark<<<(NB * L + 255) / 256, 256>>>(L, P);
        k_pxcompact<<<(NB * P + 255) / 256, 256>>>(P);
        // phase B: exact recompute on band pixels only -> compact keys
        k_econv<<<dim3(PXCAP / GPX, NB), 256>>>(feats[l], b_conv, w_obj, b_obj,
                                                w_delta, b_delta, S, LG[l], L);
        k_select<<<NB, 1024>>>(1, 0, KL[l], 8);            // exact top-k over band keys
        k_compactb<<<dim3(BKCAP / 256, NB), 256>>>();
        k_sortdecode<<<NB, 1024>>>(S, LG[l], STm[l], SZ[l], l, KL[l], OFF[l], L);
    }

    k_rank<<<dim3((MTOT + 255) / 256, NB), 256>>>();
    k_mask<<<dim3(125, 5, NB), dim3(16, 8)>>>();
    k_nms<<<dim3(5, NB), 32>>>();
    k_out<<<NB, 1024>>>(out);
}